// round 15
// baseline (speedup 1.0000x reference)
#include <cuda_runtime.h>
#include <cuda_bf16.h>
#include <cstdint>

#define BATCH 8
#define CH    384
#define NHEAD 6
#define DHEAD 64
#define NTOK  1024
#define BH    (BATCH*NHEAD)

// scratch (GEMM operands pre-rounded to tf32; E stored bf16 for attn-map only)
__device__ float g_Xq[BATCH*CH*NTOK];
__device__ float g_Xc[BATCH*CH*NTOK];
__device__ float g_Wq[CH*CH];
__device__ float g_Wk[CH*CH];
__device__ float g_Wv[CH*CH];
__device__ float g_Wo[CH*CH];
__device__ float g_Qt[BATCH*NTOK*CH];                 // token-major [b][n][inner]
__device__ float g_Kc[BATCH*CH*NTOK];                 // channel-major
__device__ float g_Vt[BATCH*NTOK*CH];                 // token-major
__device__ float g_O [BATCH*CH*NTOK];                 // channel-major
__device__ __nv_bfloat16 g_Eb[(size_t)BH*NTOK*NTOK];  // exp(logits) bf16 (colsum only)
__device__ float g_linv[BH*NTOK];
__device__ float g_colsum[BATCH*NTOK];

__device__ __forceinline__ uint32_t smem_u32(const void* p) {
    uint32_t a;
    asm("{ .reg .u64 t; cvta.to.shared.u64 t, %1; cvt.u32.u64 %0, t; }" : "=r"(a) : "l"(p));
    return a;
}
__device__ __forceinline__ float tf32r(float x) {
    uint32_t b;
    asm("cvt.rna.tf32.f32 %0, %1;" : "=r"(b) : "f"(x));
    return __uint_as_float(b);
}
__device__ __forceinline__ void cpa16(uint32_t d, const void* s) {
    asm volatile("cp.async.ca.shared.global [%0], [%1], 16;" :: "r"(d), "l"(s));
}
#define CP_COMMIT() asm volatile("cp.async.commit_group;" ::: "memory")
#define CP_WAIT1()  asm volatile("cp.async.wait_group 1;" ::: "memory")
#define CP_WAIT0()  asm volatile("cp.async.wait_group 0;" ::: "memory")

__device__ __forceinline__ void mma8(float* d, const uint32_t* a, const uint32_t* b) {
    asm volatile("mma.sync.aligned.m16n8k8.row.col.f32.tf32.tf32.f32 "
        "{%0,%1,%2,%3}, {%4,%5,%6,%7}, {%8,%9}, {%0,%1,%2,%3};"
        : "+f"(d[0]), "+f"(d[1]), "+f"(d[2]), "+f"(d[3])
        : "r"(a[0]), "r"(a[1]), "r"(a[2]), "r"(a[3]), "r"(b[0]), "r"(b[1]));
}
#define LDU(p) (*(const uint32_t*)(p))

// ---------------------------------------------------------------------------
// one launch rounds both inputs; also zeroes colsum
__global__ void k_round2(const float* __restrict__ q, const float* __restrict__ c) {
    const size_t i4 = (size_t)blockIdx.x * 256 + threadIdx.x;
    const float* s = blockIdx.y ? c : q;
    float* d = blockIdx.y ? g_Xc : g_Xq;
    float4 v = *((const float4*)s + i4);
    v.x = tf32r(v.x); v.y = tf32r(v.y); v.z = tf32r(v.z); v.w = tf32r(v.w);
    *((float4*)d + i4) = v;
    if (blockIdx.y == 0 && i4 < BATCH * NTOK / 4)
        *((float4*)g_colsum + i4) = make_float4(0.f, 0.f, 0.f, 0.f);
}

__global__ void k_roundW(const float* __restrict__ wq, const float* __restrict__ wk,
                         const float* __restrict__ wv, const float* __restrict__ wo) {
    const int i4 = blockIdx.x * 256 + threadIdx.x;
    const float* s; float* d;
    switch (blockIdx.y) {
        case 0: s = wq; d = g_Wq; break;
        case 1: s = wk; d = g_Wk; break;
        case 2: s = wv; d = g_Wv; break;
        default: s = wo; d = g_Wo; break;
    }
    float4 v = *((const float4*)s + i4);
    v.x = tf32r(v.x); v.y = tf32r(v.y); v.z = tf32r(v.z); v.w = tf32r(v.w);
    *((float4*)d + i4) = v;
}

__global__ void k_amap(float* __restrict__ out) {
    const int idx = blockIdx.x * 256 + threadIdx.x;
    out[(size_t)BATCH * CH * NTOK + idx] = g_colsum[idx] * (1.0f / (NHEAD * NTOK));
}

// colsum from bf16 E (attn-map path): colsum[b][j] += sum_i E[i][j]*linv[i]
__global__ __launch_bounds__(256) void k_colsum() {
    __shared__ float rx[256], ry[256];
    const int t = threadIdx.x;
    const int bh = blockIdx.y, b = bh / NHEAD;
    const int jj = blockIdx.x * 64 + (t & 63);       // bf162 index
    const int q = t >> 6;                            // quarter: 256 rows each
    const __nv_bfloat162* E2 =
        (const __nv_bfloat162*)(g_Eb + (size_t)bh * NTOK * NTOK);
    const float* li = g_linv + bh * NTOK;
    float sx = 0.f, sy = 0.f;
    for (int i = q * 256; i < q * 256 + 256; i++) {
        const __nv_bfloat162 e = E2[(size_t)i * 512 + jj];
        const float l = li[i];
        sx += __bfloat162float(e.x) * l;
        sy += __bfloat162float(e.y) * l;
    }
    rx[t] = sx; ry[t] = sy;
    __syncthreads();
    if (t < 64) {
        const float vx = rx[t] + rx[t + 64] + rx[t + 128] + rx[t + 192];
        const float vy = ry[t] + ry[t + 64] + ry[t + 128] + ry[t + 192];
        const int j = blockIdx.x * 128 + t * 2;
        atomicAdd(&g_colsum[b * NTOK + j], vx);
        atomicAdd(&g_colsum[b * NTOK + j + 1], vy);
    }
}

// ---------------------------------------------------------------------------
// Fused projection GEMMs. D[m][n] = sum_k A[m][k]*B[b][k][n]. grid z = nw*BATCH.
// mode 0: token-major tf32; 1: channel-major tf32; 2: channel-major + bias raw
struct MMArgs {
    const float* A[3]; const float* B[3]; float* Y[3];
    const float* bias; int mode[3];
};

__global__ __launch_bounds__(256, 2)
void k_mm(MMArgs args) {
    extern __shared__ float sm[];
    float (*As)[36]  = (float(*)[36])sm;               // [2][128][36]
    float (*Bs)[136] = (float(*)[136])(sm + 2*128*36); // [2][32][136]
    const uint32_t sbA = smem_u32(sm), sbB = smem_u32(sm + 2*128*36);

    const int t = threadIdx.x, lane = t & 31, wid = t >> 5;
    const int g = lane >> 2, tig = lane & 3;
    const int wm = wid >> 1, wn = wid & 1;
    const int w = blockIdx.z / BATCH, b = blockIdx.z % BATCH;
    const int n0 = blockIdx.x * 128, m0 = blockIdx.y * 128;
    const float* Aw = args.A[w];
    const float* Bb = args.B[w] + (size_t)b * CH * NTOK;
    const int mode = args.mode[w];

    float acc[2][8][4] = {};

    #pragma unroll
    for (int it = 0; it < 4; it++) {
        const int idx = t + 256 * it, r = idx >> 3, f = idx & 7;
        cpa16(sbA + (r * 36 + f * 4) * 4, &Aw[(size_t)(m0 + r) * CH + f * 4]);
    }
    #pragma unroll
    for (int it = 0; it < 4; it++) {
        const int idx = t + 256 * it, r = idx >> 5, f = idx & 31;
        cpa16(sbB + (r * 136 + f * 4) * 4, &Bb[(size_t)r * NTOK + n0 + f * 4]);
    }
    CP_COMMIT();

    for (int c = 0; c < 12; c++) {
        const int buf = c & 1;
        if (c + 1 < 12) {
            const int k1 = (c + 1) * 32, nb = (c + 1) & 1;
            #pragma unroll
            for (int it = 0; it < 4; it++) {
                const int idx = t + 256 * it, r = idx >> 3, f = idx & 7;
                cpa16(sbA + nb * 18432 + (r * 36 + f * 4) * 4,
                      &Aw[(size_t)(m0 + r) * CH + k1 + f * 4]);
            }
            #pragma unroll
            for (int it = 0; it < 4; it++) {
                const int idx = t + 256 * it, r = idx >> 5, f = idx & 31;
                cpa16(sbB + nb * 17408 + (r * 136 + f * 4) * 4,
                      &Bb[(size_t)(k1 + r) * NTOK + n0 + f * 4]);
            }
            CP_COMMIT();
            CP_WAIT1();
        } else {
            CP_WAIT0();
        }
        __syncthreads();
        #pragma unroll
        for (int ks = 0; ks < 4; ks++) {
            const int kk = ks * 8;
            uint32_t af[2][4], bf[8][2];
            #pragma unroll
            for (int mf = 0; mf < 2; mf++) {
                const int rb = buf * 128 + wm * 32 + mf * 16 + g;
                af[mf][0] = LDU(&As[rb][kk + tig]);
                af[mf][1] = LDU(&As[rb + 8][kk + tig]);
                af[mf][2] = LDU(&As[rb][kk + tig + 4]);
                af[mf][3] = LDU(&As[rb + 8][kk + tig + 4]);
            }
            #pragma unroll
            for (int nf = 0; nf < 8; nf++) {
                const int col = wn * 64 + nf * 8 + g;
                bf[nf][0] = LDU(&Bs[buf * 32 + kk + tig][col]);
                bf[nf][1] = LDU(&Bs[buf * 32 + kk + tig + 4][col]);
            }
            #pragma unroll
            for (int mf = 0; mf < 2; mf++)
                #pragma unroll
                for (int nf = 0; nf < 8; nf++)
                    mma8(acc[mf][nf], af[mf], bf[nf]);
        }
        __syncthreads();
    }

    if (mode == 0) {
        float* Yb = args.Y[w] + (size_t)b * NTOK * CH;
        #pragma unroll
        for (int mf = 0; mf < 2; mf++) {
            const int r0 = m0 + wm * 32 + mf * 16 + g, r1 = r0 + 8;
            #pragma unroll
            for (int nf = 0; nf < 8; nf++) {
                const int col = n0 + wn * 64 + nf * 8 + tig * 2;
                Yb[(size_t)col * CH + r0]       = tf32r(acc[mf][nf][0]);
                Yb[(size_t)(col + 1) * CH + r0] = tf32r(acc[mf][nf][1]);
                Yb[(size_t)col * CH + r1]       = tf32r(acc[mf][nf][2]);
                Yb[(size_t)(col + 1) * CH + r1] = tf32r(acc[mf][nf][3]);
            }
        }
    } else {
        float* Yb = args.Y[w] + (size_t)b * CH * NTOK;
        const bool wb = (mode == 2);
        #pragma unroll
        for (int mf = 0; mf < 2; mf++) {
            const int r0 = m0 + wm * 32 + mf * 16 + g, r1 = r0 + 8;
            const float b0 = wb ? args.bias[r0] : 0.0f;
            const float b1 = wb ? args.bias[r1] : 0.0f;
            #pragma unroll
            for (int nf = 0; nf < 8; nf++) {
                const int col = n0 + wn * 64 + nf * 8 + tig * 2;
                float2 v0, v1;
                if (wb) {
                    v0 = make_float2(acc[mf][nf][0] + b0, acc[mf][nf][1] + b0);
                    v1 = make_float2(acc[mf][nf][2] + b1, acc[mf][nf][3] + b1);
                } else {
                    v0 = make_float2(tf32r(acc[mf][nf][0]), tf32r(acc[mf][nf][1]));
                    v1 = make_float2(tf32r(acc[mf][nf][2]), tf32r(acc[mf][nf][3]));
                }
                *(float2*)&Yb[(size_t)r0 * NTOK + col] = v0;
                *(float2*)&Yb[(size_t)r1 * NTOK + col] = v1;
            }
        }
    }
}

// ---------------------------------------------------------------------------
// Fused attention, R8 tiling (256 thr, 8 warps 4wm x 2wn, warp 32i x 64j) but:
//  - quarter nf-split (2 nf per S->exp->PV pass) -> live sacc = 16 floats
//  - single-buffered K/V -> smem 108 KB -> 2 CTAs/SM
//  - __launch_bounds__(256, 2) forces the 128-reg target
__global__ __launch_bounds__(256, 2)
void k_attn() {
    extern __shared__ float sm[];
    float (*Qs)[68]  = (float(*)[68])sm;              // [128][68]   (reused as Os)
    float (*Ks)[136] = (float(*)[136])(sm + 8704);    // [64][136] single buffer
    float (*Vs)[72]  = (float(*)[72])(sm + 17408);    // [128][72] single buffer
    float* red    = sm + 26624;                       // [256]
    float* linv_s = sm + 26880;                       // [128]  (total 27008 fl)
    const uint32_t sbK = smem_u32(sm + 8704), sbV = smem_u32(sm + 17408);

    const int t = threadIdx.x, lane = t & 31, wid = t >> 5;
    const int g = lane >> 2, tig = lane & 3;
    const int wm = wid >> 1, wn = wid & 1;
    const int bh = blockIdx.y, b = bh / NHEAD, h = bh % NHEAD;
    const int i0 = blockIdx.x * 128;
    const float* Qb = g_Qt + (size_t)b * NTOK * CH + h * DHEAD;
    const float* Kb = g_Kc + (size_t)b * CH * NTOK + (size_t)h * DHEAD * NTOK;
    const float* Vb = g_Vt + (size_t)b * NTOK * CH + h * DHEAD;
    __nv_bfloat16* Eb = g_Eb + (size_t)bh * NTOK * NTOK;

    #pragma unroll
    for (int it = 0; it < 8; it++) {                  // Q tile 128 x 64
        const int idx = t + 256 * it, r = idx >> 4, f = idx & 15;
        *(float4*)&Qs[r][f * 4] = *(const float4*)&Qb[(size_t)(i0 + r) * CH + f * 4];
    }
    #pragma unroll
    for (int it = 0; it < 8; it++) {                  // K tile 0 (64 x 128)
        const int idx = t + 256 * it, r = idx >> 5, f = idx & 31;
        cpa16(sbK + (r * 136 + f * 4) * 4, &Kb[(size_t)r * NTOK + f * 4]);
    }
    #pragma unroll
    for (int it = 0; it < 8; it++) {                  // V tile 0 (128 x 64)
        const int idx = t + 256 * it, r = idx >> 4, f = idx & 15;
        cpa16(sbV + (r * 72 + f * 4) * 4, &Vb[(size_t)r * CH + f * 4]);
    }
    CP_COMMIT();

    float pv[2][8][4] = {};
    float rs[2][2] = {};
    const int sh1 = (lane & ~3) + (tig >> 1), sh2 = sh1 + 2;
    const bool odd = tig & 1;

    for (int jt = 0; jt < 8; jt++) {
        const int j0 = jt * 128;
        CP_WAIT0();
        __syncthreads();

        // four nf-quarters: S-MMA(2 nf) -> exp/E -> PV(2 nf). Live sacc = 16.
        #pragma unroll
        for (int qtr = 0; qtr < 4; qtr++) {
            float sacc[2][2][4] = {};
            #pragma unroll
            for (int ks = 0; ks < 8; ks++) {
                const int kk = ks * 8;
                uint32_t af[2][4], bf[2][2];
                #pragma unroll
                for (int mf = 0; mf < 2; mf++) {
                    const int rb = wm * 32 + mf * 16 + g;
                    af[mf][0] = LDU(&Qs[rb][kk + tig]);
                    af[mf][1] = LDU(&Qs[rb + 8][kk + tig]);
                    af[mf][2] = LDU(&Qs[rb][kk + tig + 4]);
                    af[mf][3] = LDU(&Qs[rb + 8][kk + tig + 4]);
                }
                #pragma unroll
                for (int nf = 0; nf < 2; nf++) {
                    const int col = wn * 64 + (qtr * 2 + nf) * 8 + g;
                    bf[nf][0] = LDU(&Ks[kk + tig][col]);
                    bf[nf][1] = LDU(&Ks[kk + tig + 4][col]);
                }
                #pragma unroll
                for (int mf = 0; mf < 2; mf++)
                    #pragma unroll
                    for (int nf = 0; nf < 2; nf++)
                        mma8(sacc[mf][nf], af[mf], bf[nf]);
            }

            // exp, rowsum, bf16 E store; sacc becomes tf32(P)
            #pragma unroll
            for (int mf = 0; mf < 2; mf++) {
                const int r0 = wm * 32 + mf * 16 + g, r1 = r0 + 8;
                #pragma unroll
                for (int nf = 0; nf < 2; nf++) {
                    const int col = j0 + wn * 64 + (qtr * 2 + nf) * 8 + tig * 2;
                    const float e0 = __expf(sacc[mf][nf][0] * 0.125f);
                    const float e1 = __expf(sacc[mf][nf][1] * 0.125f);
                    const float e2 = __expf(sacc[mf][nf][2] * 0.125f);
                    const float e3 = __expf(sacc[mf][nf][3] * 0.125f);
                    rs[mf][0] += e0 + e1;
                    rs[mf][1] += e2 + e3;
                    *(__nv_bfloat162*)&Eb[(size_t)(i0 + r0) * NTOK + col] =
                        __floats2bfloat162_rn(e0, e1);
                    *(__nv_bfloat162*)&Eb[(size_t)(i0 + r1) * NTOK + col] =
                        __floats2bfloat162_rn(e2, e3);
                    sacc[mf][nf][0] = tf32r(e0);
                    sacc[mf][nf][1] = tf32r(e1);
                    sacc[mf][nf][2] = tf32r(e2);
                    sacc[mf][nf][3] = tf32r(e3);
                }
            }

            // PV partial over this quarter's 16 j-columns
            #pragma unroll
            for (int nf = 0; nf < 2; nf++) {
                const int kp = wn * 64 + (qtr * 2 + nf) * 8;
                uint32_t bf[8][2];
                #pragma unroll
                for (int dn = 0; dn < 8; dn++) {
                    bf[dn][0] = LDU(&Vs[kp + tig][dn * 8 + g]);
                    bf[dn][1] = LDU(&Vs[kp + tig + 4][dn * 8 + g]);
                }
                #pragma unroll
                for (int mf = 0; mf < 2; mf++) {
                    const float c0 = sacc[mf][nf][0], c1 = sacc[mf][nf][1];
                    const float c2 = sacc[mf][nf][2], c3 = sacc[mf][nf][3];
                    const float x0 = __shfl_sync(0xffffffffu, c0, sh1);
                    const float x1 = __shfl_sync(0xffffffffu, c1, sh1);
                    const float x2 = __shfl_sync(0xffffffffu, c2, sh1);
                    const float x3 = __shfl_sync(0xffffffffu, c3, sh1);
                    const float y0 = __shfl_sync(0xffffffffu, c0, sh2);
                    const float y1 = __shfl_sync(0xffffffffu, c1, sh2);
                    const float y2 = __shfl_sync(0xffffffffu, c2, sh2);
                    const float y3 = __shfl_sync(0xffffffffu, c3, sh2);
                    uint32_t af[4];
                    af[0] = __float_as_uint(odd ? x1 : x0);
                    af[1] = __float_as_uint(odd ? x3 : x2);
                    af[2] = __float_as_uint(odd ? y1 : y0);
                    af[3] = __float_as_uint(odd ? y3 : y2);
                    #pragma unroll
                    for (int dn = 0; dn < 8; dn++)
                        mma8(pv[mf][dn], af, bf[dn]);
                }
            }
        }

        // all reads of Ks/Vs done -> safe to overwrite; issue next tile loads
        __syncthreads();
        if (jt + 1 < 8) {
            const int j1 = (jt + 1) * 128;
            #pragma unroll
            for (int it = 0; it < 8; it++) {
                const int idx = t + 256 * it, r = idx >> 5, f = idx & 31;
                cpa16(sbK + (r * 136 + f * 4) * 4,
                      &Kb[(size_t)r * NTOK + j1 + f * 4]);
            }
            #pragma unroll
            for (int it = 0; it < 8; it++) {
                const int idx = t + 256 * it, r = idx >> 4, f = idx & 15;
                cpa16(sbV + (r * 72 + f * 4) * 4,
                      &Vb[(size_t)(j1 + r) * CH + f * 4]);
            }
            CP_COMMIT();
        }
    }

    // ---- rowsum -> linv ----
    #pragma unroll
    for (int mf = 0; mf < 2; mf++)
        #pragma unroll
        for (int hf = 0; hf < 2; hf++) {
            rs[mf][hf] += __shfl_xor_sync(0xffffffffu, rs[mf][hf], 1);
            rs[mf][hf] += __shfl_xor_sync(0xffffffffu, rs[mf][hf], 2);
        }
    if (tig == 0) {
        #pragma unroll
        for (int mf = 0; mf < 2; mf++) {
            red[wn * 128 + wm * 32 + mf * 16 + g]     = rs[mf][0];
            red[wn * 128 + wm * 32 + mf * 16 + g + 8] = rs[mf][1];
        }
    }
    __syncthreads();
    if (t < 128) {
        const float li = 1.0f / (red[t] + red[128 + t]);
        g_linv[bh * NTOK + i0 + t] = li;
        linv_s[t] = li;
    }
    // wn1 stages its PV partial into Qs (Q no longer needed)
    if (wn == 1) {
        #pragma unroll
        for (int mf = 0; mf < 2; mf++) {
            const int lr0 = wm * 32 + mf * 16 + g, lr1 = lr0 + 8;
            #pragma unroll
            for (int dn = 0; dn < 8; dn++) {
                const int col = dn * 8 + tig * 2;
                *(float2*)&Qs[lr0][col] = make_float2(pv[mf][dn][0], pv[mf][dn][1]);
                *(float2*)&Qs[lr1][col] = make_float2(pv[mf][dn][2], pv[mf][dn][3]);
            }
        }
    }
    __syncthreads();
    if (wn == 0) {
        float* Ob = g_O + ((size_t)b * CH + h * DHEAD) * NTOK;
        #pragma unroll
        for (int mf = 0; mf < 2; mf++) {
            const int lr0 = wm * 32 + mf * 16 + g, lr1 = lr0 + 8;
            const float li0 = linv_s[lr0], li1 = linv_s[lr1];
            #pragma unroll
            for (int dn = 0; dn < 8; dn++) {
                const int col = dn * 8 + tig * 2;
                Ob[(size_t)col * NTOK + i0 + lr0] =
                    tf32r((pv[mf][dn][0] + Qs[lr0][col]) * li0);
                Ob[(size_t)(col + 1) * NTOK + i0 + lr0] =
                    tf32r((pv[mf][dn][1] + Qs[lr0][col + 1]) * li0);
                Ob[(size_t)col * NTOK + i0 + lr1] =
                    tf32r((pv[mf][dn][2] + Qs[lr1][col]) * li1);
                Ob[(size_t)(col + 1) * NTOK + i0 + lr1] =
                    tf32r((pv[mf][dn][3] + Qs[lr1][col + 1]) * li1);
            }
        }
    }
}

// ---------------------------------------------------------------------------
extern "C" void kernel_launch(void* const* d_in, const int* in_sizes, int n_in,
                              void* d_out, int out_size) {
    const float* query   = (const float*)d_in[0];
    const float* context = (const float*)d_in[1];
    const float* Wq      = (const float*)d_in[2];
    const float* Wk      = (const float*)d_in[3];
    const float* Wv      = (const float*)d_in[4];
    const float* Wo      = (const float*)d_in[5];
    const float* bo      = (const float*)d_in[6];
    float* out = (float*)d_out;

    const int SM_MM   = (2*128*36 + 2*32*136) * 4;   // 71680
    const int SM_ATTN = 27008 * 4;                   // 108032 -> 2 CTAs/SM
    cudaFuncSetAttribute(k_mm,   cudaFuncAttributeMaxDynamicSharedMemorySize, SM_MM);
    cudaFuncSetAttribute(k_attn, cudaFuncAttributeMaxDynamicSharedMemorySize, SM_ATTN);

    float *pXq, *pXc, *pWq, *pWk, *pWv, *pWo, *pQt, *pKc, *pVt, *pO;
    cudaGetSymbolAddress((void**)&pXq, g_Xq);
    cudaGetSymbolAddress((void**)&pXc, g_Xc);
    cudaGetSymbolAddress((void**)&pWq, g_Wq);
    cudaGetSymbolAddress((void**)&pWk, g_Wk);
    cudaGetSymbolAddress((void**)&pWv, g_Wv);
    cudaGetSymbolAddress((void**)&pWo, g_Wo);
    cudaGetSymbolAddress((void**)&pQt, g_Qt);
    cudaGetSymbolAddress((void**)&pKc, g_Kc);
    cudaGetSymbolAddress((void**)&pVt, g_Vt);
    cudaGetSymbolAddress((void**)&pO,  g_O);

    k_round2<<<dim3(BATCH * CH * NTOK / 1024, 2), 256>>>(query, context);
    k_roundW<<<dim3(CH * CH / 1024, 4), 256>>>(Wq, Wk, Wv, Wo);

    MMArgs a1;
    a1.A[0] = pWq; a1.B[0] = pXq; a1.Y[0] = pQt; a1.mode[0] = 0;
    a1.A[1] = pWk; a1.B[1] = pXc; a1.Y[1] = pKc; a1.mode[1] = 1;
    a1.A[2] = pWv; a1.B[2] = pXc; a1.Y[2] = pVt; a1.mode[2] = 0;
    a1.bias = nullptr;
    k_mm<<<dim3(8, 3, 24), 256, SM_MM>>>(a1);

    k_attn<<<dim3(8, BH), 256, SM_ATTN>>>();
    k_colsum<<<dim3(8, BH), 256>>>();

    MMArgs a2;
    a2.A[0] = pWo; a2.B[0] = pO; a2.Y[0] = out; a2.mode[0] = 2;
    a2.A[1] = a2.A[2] = nullptr; a2.B[1] = a2.B[2] = nullptr;
    a2.Y[1] = a2.Y[2] = nullptr; a2.mode[1] = a2.mode[2] = 0;
    a2.bias = bo;
    k_mm<<<dim3(8, 3, 8), 256, SM_MM>>>(a2);

    k_amap<<<BATCH * NTOK / 256, 256>>>(out);
}

// round 16
// speedup vs baseline: 1.6595x; 1.6595x over previous
#include <cuda_runtime.h>
#include <cuda_bf16.h>
#include <cstdint>

#define BATCH 8
#define CH    384
#define NHEAD 6
#define DHEAD 64
#define NTOK  1024
#define BH    (BATCH*NHEAD)

// scratch (GEMM operands pre-rounded to tf32; E stored bf16 for attn-map only)
__device__ float g_Xq[BATCH*CH*NTOK];
__device__ float g_Xc[BATCH*CH*NTOK];
__device__ float g_Wq[CH*CH];
__device__ float g_Wk[CH*CH];
__device__ float g_Wv[CH*CH];
__device__ float g_Wo[CH*CH];
__device__ float g_Qt[BATCH*NTOK*CH];                 // token-major [b][n][inner]
__device__ float g_Kc[BATCH*CH*NTOK];                 // channel-major
__device__ float g_Vt[BATCH*NTOK*CH];                 // token-major
__device__ float g_O [BATCH*CH*NTOK];                 // channel-major
__device__ __nv_bfloat16 g_Eb[(size_t)BH*NTOK*NTOK];  // exp(logits) bf16 (colsum only)
__device__ float g_linv[BH*NTOK];
__device__ float g_colsum[BATCH*NTOK];

__device__ __forceinline__ uint32_t smem_u32(const void* p) {
    uint32_t a;
    asm("{ .reg .u64 t; cvta.to.shared.u64 t, %1; cvt.u32.u64 %0, t; }" : "=r"(a) : "l"(p));
    return a;
}
__device__ __forceinline__ float tf32r(float x) {
    uint32_t b;
    asm("cvt.rna.tf32.f32 %0, %1;" : "=r"(b) : "f"(x));
    return __uint_as_float(b);
}
__device__ __forceinline__ void cpa16(uint32_t d, const void* s) {
    asm volatile("cp.async.ca.shared.global [%0], [%1], 16;" :: "r"(d), "l"(s));
}
#define CP_COMMIT() asm volatile("cp.async.commit_group;" ::: "memory")
#define CP_WAIT1()  asm volatile("cp.async.wait_group 1;" ::: "memory")
#define CP_WAIT0()  asm volatile("cp.async.wait_group 0;" ::: "memory")

__device__ __forceinline__ void mma8(float* d, const uint32_t* a, const uint32_t* b) {
    asm volatile("mma.sync.aligned.m16n8k8.row.col.f32.tf32.tf32.f32 "
        "{%0,%1,%2,%3}, {%4,%5,%6,%7}, {%8,%9}, {%0,%1,%2,%3};"
        : "+f"(d[0]), "+f"(d[1]), "+f"(d[2]), "+f"(d[3])
        : "r"(a[0]), "r"(a[1]), "r"(a[2]), "r"(a[3]), "r"(b[0]), "r"(b[1]));
}
#define LDU(p) (*(const uint32_t*)(p))

// ---------------------------------------------------------------------------
// one launch rounds both inputs; also zeroes colsum
__global__ void k_round2(const float* __restrict__ q, const float* __restrict__ c) {
    const size_t i4 = (size_t)blockIdx.x * 256 + threadIdx.x;
    const float* s = blockIdx.y ? c : q;
    float* d = blockIdx.y ? g_Xc : g_Xq;
    float4 v = *((const float4*)s + i4);
    v.x = tf32r(v.x); v.y = tf32r(v.y); v.z = tf32r(v.z); v.w = tf32r(v.w);
    *((float4*)d + i4) = v;
    if (blockIdx.y == 0 && i4 < BATCH * NTOK / 4)
        *((float4*)g_colsum + i4) = make_float4(0.f, 0.f, 0.f, 0.f);
}

__global__ void k_roundW(const float* __restrict__ wq, const float* __restrict__ wk,
                         const float* __restrict__ wv, const float* __restrict__ wo) {
    const int i4 = blockIdx.x * 256 + threadIdx.x;
    const float* s; float* d;
    switch (blockIdx.y) {
        case 0: s = wq; d = g_Wq; break;
        case 1: s = wk; d = g_Wk; break;
        case 2: s = wv; d = g_Wv; break;
        default: s = wo; d = g_Wo; break;
    }
    float4 v = *((const float4*)s + i4);
    v.x = tf32r(v.x); v.y = tf32r(v.y); v.z = tf32r(v.z); v.w = tf32r(v.w);
    *((float4*)d + i4) = v;
}

__global__ void k_amap(float* __restrict__ out) {
    const int idx = blockIdx.x * 256 + threadIdx.x;
    out[(size_t)BATCH * CH * NTOK + idx] = g_colsum[idx] * (1.0f / (NHEAD * NTOK));
}

// colsum from bf16 E (attn-map path): colsum[b][j] += sum_i E[i][j]*linv[i]
__global__ __launch_bounds__(256) void k_colsum() {
    __shared__ float rx[256], ry[256];
    const int t = threadIdx.x;
    const int bh = blockIdx.y, b = bh / NHEAD;
    const int jj = blockIdx.x * 64 + (t & 63);       // bf162 index
    const int q = t >> 6;                            // quarter: 256 rows each
    const __nv_bfloat162* E2 =
        (const __nv_bfloat162*)(g_Eb + (size_t)bh * NTOK * NTOK);
    const float* li = g_linv + bh * NTOK;
    float sx = 0.f, sy = 0.f;
    for (int i = q * 256; i < q * 256 + 256; i++) {
        const __nv_bfloat162 e = E2[(size_t)i * 512 + jj];
        const float l = li[i];
        sx += __bfloat162float(e.x) * l;
        sy += __bfloat162float(e.y) * l;
    }
    rx[t] = sx; ry[t] = sy;
    __syncthreads();
    if (t < 64) {
        const float vx = rx[t] + rx[t + 64] + rx[t + 128] + rx[t + 192];
        const float vy = ry[t] + ry[t + 64] + ry[t + 128] + ry[t + 192];
        const int j = blockIdx.x * 128 + t * 2;
        atomicAdd(&g_colsum[b * NTOK + j], vx);
        atomicAdd(&g_colsum[b * NTOK + j + 1], vy);
    }
}

// ---------------------------------------------------------------------------
// Fused projection GEMMs. D[m][n] = sum_k A[m][k]*B[b][k][n]. grid z = nw*BATCH.
// mode 0: token-major tf32 (smem-staged coalesced epilogue);
// mode 1: channel-major tf32; mode 2: channel-major + bias raw
struct MMArgs {
    const float* A[3]; const float* B[3]; float* Y[3];
    const float* bias; int mode[3];
};

__global__ __launch_bounds__(256, 2)
void k_mm(MMArgs args) {
    extern __shared__ float sm[];
    float (*As)[36]  = (float(*)[36])sm;               // [2][128][36]
    float (*Bs)[136] = (float(*)[136])(sm + 2*128*36); // [2][32][136]
    const uint32_t sbA = smem_u32(sm), sbB = smem_u32(sm + 2*128*36);

    const int t = threadIdx.x, lane = t & 31, wid = t >> 5;
    const int g = lane >> 2, tig = lane & 3;
    const int wm = wid >> 1, wn = wid & 1;
    const int w = blockIdx.z / BATCH, b = blockIdx.z % BATCH;
    const int n0 = blockIdx.x * 128, m0 = blockIdx.y * 128;
    const float* Aw = args.A[w];
    const float* Bb = args.B[w] + (size_t)b * CH * NTOK;
    const int mode = args.mode[w];

    float acc[2][8][4] = {};

    #pragma unroll
    for (int it = 0; it < 4; it++) {
        const int idx = t + 256 * it, r = idx >> 3, f = idx & 7;
        cpa16(sbA + (r * 36 + f * 4) * 4, &Aw[(size_t)(m0 + r) * CH + f * 4]);
    }
    #pragma unroll
    for (int it = 0; it < 4; it++) {
        const int idx = t + 256 * it, r = idx >> 5, f = idx & 31;
        cpa16(sbB + (r * 136 + f * 4) * 4, &Bb[(size_t)r * NTOK + n0 + f * 4]);
    }
    CP_COMMIT();

    for (int c = 0; c < 12; c++) {
        const int buf = c & 1;
        if (c + 1 < 12) {
            const int k1 = (c + 1) * 32, nb = (c + 1) & 1;
            #pragma unroll
            for (int it = 0; it < 4; it++) {
                const int idx = t + 256 * it, r = idx >> 3, f = idx & 7;
                cpa16(sbA + nb * 18432 + (r * 36 + f * 4) * 4,
                      &Aw[(size_t)(m0 + r) * CH + k1 + f * 4]);
            }
            #pragma unroll
            for (int it = 0; it < 4; it++) {
                const int idx = t + 256 * it, r = idx >> 5, f = idx & 31;
                cpa16(sbB + nb * 17408 + (r * 136 + f * 4) * 4,
                      &Bb[(size_t)(k1 + r) * NTOK + n0 + f * 4]);
            }
            CP_COMMIT();
            CP_WAIT1();
        } else {
            CP_WAIT0();
        }
        __syncthreads();
        #pragma unroll
        for (int ks = 0; ks < 4; ks++) {
            const int kk = ks * 8;
            uint32_t af[2][4], bf[8][2];
            #pragma unroll
            for (int mf = 0; mf < 2; mf++) {
                const int rb = buf * 128 + wm * 32 + mf * 16 + g;
                af[mf][0] = LDU(&As[rb][kk + tig]);
                af[mf][1] = LDU(&As[rb + 8][kk + tig]);
                af[mf][2] = LDU(&As[rb][kk + tig + 4]);
                af[mf][3] = LDU(&As[rb + 8][kk + tig + 4]);
            }
            #pragma unroll
            for (int nf = 0; nf < 8; nf++) {
                const int col = wn * 64 + nf * 8 + g;
                bf[nf][0] = LDU(&Bs[buf * 32 + kk + tig][col]);
                bf[nf][1] = LDU(&Bs[buf * 32 + kk + tig + 4][col]);
            }
            #pragma unroll
            for (int mf = 0; mf < 2; mf++)
                #pragma unroll
                for (int nf = 0; nf < 8; nf++)
                    mma8(acc[mf][nf], af[mf], bf[nf]);
        }
        __syncthreads();
    }

    if (mode == 0) {
        // stage [n][m] tile in smem (As/Bs dead), then coalesced writes.
        float* stage = sm;   // 128 rows x stride 132 = 16896 floats < 17920 avail
        #pragma unroll
        for (int mf = 0; mf < 2; mf++) {
            const int r0 = wm * 32 + mf * 16 + g, r1 = r0 + 8;
            #pragma unroll
            for (int nf = 0; nf < 8; nf++) {
                const int col = wn * 64 + nf * 8 + tig * 2;
                stage[(col    ) * 132 + r0] = tf32r(acc[mf][nf][0]);
                stage[(col + 1) * 132 + r0] = tf32r(acc[mf][nf][1]);
                stage[(col    ) * 132 + r1] = tf32r(acc[mf][nf][2]);
                stage[(col + 1) * 132 + r1] = tf32r(acc[mf][nf][3]);
            }
        }
        __syncthreads();
        float* Yb = args.Y[w] + (size_t)b * NTOK * CH;
        #pragma unroll
        for (int it = 0; it < 16; it++) {
            const int idx = t + 256 * it, n = idx >> 5, fm = idx & 31;
            *(float4*)&Yb[(size_t)(n0 + n) * CH + m0 + fm * 4] =
                *(float4*)&stage[n * 132 + fm * 4];
        }
    } else {
        float* Yb = args.Y[w] + (size_t)b * CH * NTOK;
        const bool wb = (mode == 2);
        #pragma unroll
        for (int mf = 0; mf < 2; mf++) {
            const int r0 = m0 + wm * 32 + mf * 16 + g, r1 = r0 + 8;
            const float b0 = wb ? args.bias[r0] : 0.0f;
            const float b1 = wb ? args.bias[r1] : 0.0f;
            #pragma unroll
            for (int nf = 0; nf < 8; nf++) {
                const int col = n0 + wn * 64 + nf * 8 + tig * 2;
                float2 v0, v1;
                if (wb) {
                    v0 = make_float2(acc[mf][nf][0] + b0, acc[mf][nf][1] + b0);
                    v1 = make_float2(acc[mf][nf][2] + b1, acc[mf][nf][3] + b1);
                } else {
                    v0 = make_float2(tf32r(acc[mf][nf][0]), tf32r(acc[mf][nf][1]));
                    v1 = make_float2(tf32r(acc[mf][nf][2]), tf32r(acc[mf][nf][3]));
                }
                *(float2*)&Yb[(size_t)r0 * NTOK + col] = v0;
                *(float2*)&Yb[(size_t)r1 * NTOK + col] = v1;
            }
        }
    }
}

// ---------------------------------------------------------------------------
// Fused attention (R14 best: 256 thr, 8 warps 4wm x 2wn, warp 32i x 64j,
// two nf-halves per j-tile, double-buffered K/V, occ 1).
__global__ __launch_bounds__(256, 1)
void k_attn() {
    extern __shared__ float sm[];
    float (*Qs)[68]  = (float(*)[68])sm;              // [128][68]   (reused as Os)
    float (*Ks)[136] = (float(*)[136])(sm + 8704);    // [2][64][136]
    float (*Vs)[72]  = (float(*)[72])(sm + 26112);    // [2][128][72]
    float* red    = sm + 44544;                       // [256]
    float* linv_s = sm + 44800;                       // [128]
    const uint32_t sbK = smem_u32(sm + 8704), sbV = smem_u32(sm + 26112);

    const int t = threadIdx.x, lane = t & 31, wid = t >> 5;
    const int g = lane >> 2, tig = lane & 3;
    const int wm = wid >> 1, wn = wid & 1;
    const int bh = blockIdx.y, b = bh / NHEAD, h = bh % NHEAD;
    const int i0 = blockIdx.x * 128;
    const float* Qb = g_Qt + (size_t)b * NTOK * CH + h * DHEAD;
    const float* Kb = g_Kc + (size_t)b * CH * NTOK + (size_t)h * DHEAD * NTOK;
    const float* Vb = g_Vt + (size_t)b * NTOK * CH + h * DHEAD;
    __nv_bfloat16* Eb = g_Eb + (size_t)bh * NTOK * NTOK;

    #pragma unroll
    for (int it = 0; it < 8; it++) {                  // Q tile 128 x 64
        const int idx = t + 256 * it, r = idx >> 4, f = idx & 15;
        *(float4*)&Qs[r][f * 4] = *(const float4*)&Qb[(size_t)(i0 + r) * CH + f * 4];
    }
    #pragma unroll
    for (int it = 0; it < 8; it++) {                  // K tile 0 (64 x 128)
        const int idx = t + 256 * it, r = idx >> 5, f = idx & 31;
        cpa16(sbK + (r * 136 + f * 4) * 4, &Kb[(size_t)r * NTOK + f * 4]);
    }
    #pragma unroll
    for (int it = 0; it < 8; it++) {                  // V tile 0 (128 x 64)
        const int idx = t + 256 * it, r = idx >> 4, f = idx & 15;
        cpa16(sbV + (r * 72 + f * 4) * 4, &Vb[(size_t)r * CH + f * 4]);
    }
    CP_COMMIT();

    float pv[2][8][4] = {};
    float rs[2][2] = {};
    const int sh1 = (lane & ~3) + (tig >> 1), sh2 = sh1 + 2;
    const bool odd = tig & 1;

    for (int jt = 0; jt < 8; jt++) {
        const int j0 = jt * 128, buf = jt & 1;
        CP_WAIT0();
        __syncthreads();

        // prefetch next j-tile first (into other buffer) for max overlap
        if (jt + 1 < 8) {
            const int j1 = (jt + 1) * 128, nb = (jt + 1) & 1;
            #pragma unroll
            for (int it = 0; it < 8; it++) {
                const int idx = t + 256 * it, r = idx >> 5, f = idx & 31;
                cpa16(sbK + nb * 34816 + (r * 136 + f * 4) * 4,
                      &Kb[(size_t)r * NTOK + j1 + f * 4]);
            }
            #pragma unroll
            for (int it = 0; it < 8; it++) {
                const int idx = t + 256 * it, r = idx >> 4, f = idx & 15;
                cpa16(sbV + nb * 36864 + (r * 72 + f * 4) * 4,
                      &Vb[(size_t)(j1 + r) * CH + f * 4]);
            }
            CP_COMMIT();
        }

        // two nf-halves: S-MMA(4 nf) -> exp/E -> PV(4 nf). Halves live sacc.
        #pragma unroll
        for (int half = 0; half < 2; half++) {
            float sacc[2][4][4] = {};
            #pragma unroll
            for (int ks = 0; ks < 8; ks++) {
                const int kk = ks * 8;
                uint32_t af[2][4], bf[4][2];
                #pragma unroll
                for (int mf = 0; mf < 2; mf++) {
                    const int rb = wm * 32 + mf * 16 + g;
                    af[mf][0] = LDU(&Qs[rb][kk + tig]);
                    af[mf][1] = LDU(&Qs[rb + 8][kk + tig]);
                    af[mf][2] = LDU(&Qs[rb][kk + tig + 4]);
                    af[mf][3] = LDU(&Qs[rb + 8][kk + tig + 4]);
                }
                #pragma unroll
                for (int nf = 0; nf < 4; nf++) {
                    const int col = wn * 64 + (half * 4 + nf) * 8 + g;
                    bf[nf][0] = LDU(&Ks[buf * 64 + kk + tig][col]);
                    bf[nf][1] = LDU(&Ks[buf * 64 + kk + tig + 4][col]);
                }
                #pragma unroll
                for (int mf = 0; mf < 2; mf++)
                    #pragma unroll
                    for (int nf = 0; nf < 4; nf++)
                        mma8(sacc[mf][nf], af[mf], bf[nf]);
            }

            // exp, rowsum, bf16 E store; sacc becomes tf32(P)
            #pragma unroll
            for (int mf = 0; mf < 2; mf++) {
                const int r0 = wm * 32 + mf * 16 + g, r1 = r0 + 8;
                #pragma unroll
                for (int nf = 0; nf < 4; nf++) {
                    const int col = j0 + wn * 64 + (half * 4 + nf) * 8 + tig * 2;
                    const float e0 = __expf(sacc[mf][nf][0] * 0.125f);
                    const float e1 = __expf(sacc[mf][nf][1] * 0.125f);
                    const float e2 = __expf(sacc[mf][nf][2] * 0.125f);
                    const float e3 = __expf(sacc[mf][nf][3] * 0.125f);
                    rs[mf][0] += e0 + e1;
                    rs[mf][1] += e2 + e3;
                    *(__nv_bfloat162*)&Eb[(size_t)(i0 + r0) * NTOK + col] =
                        __floats2bfloat162_rn(e0, e1);
                    *(__nv_bfloat162*)&Eb[(size_t)(i0 + r1) * NTOK + col] =
                        __floats2bfloat162_rn(e2, e3);
                    sacc[mf][nf][0] = tf32r(e0);
                    sacc[mf][nf][1] = tf32r(e1);
                    sacc[mf][nf][2] = tf32r(e2);
                    sacc[mf][nf][3] = tf32r(e3);
                }
            }

            // PV partial over this half's 32 j-columns
            #pragma unroll
            for (int nf = 0; nf < 4; nf++) {
                const int kp = wn * 64 + (half * 4 + nf) * 8;
                uint32_t bf[8][2];
                #pragma unroll
                for (int dn = 0; dn < 8; dn++) {
                    bf[dn][0] = LDU(&Vs[buf * 128 + kp + tig][dn * 8 + g]);
                    bf[dn][1] = LDU(&Vs[buf * 128 + kp + tig + 4][dn * 8 + g]);
                }
                #pragma unroll
                for (int mf = 0; mf < 2; mf++) {
                    const float c0 = sacc[mf][nf][0], c1 = sacc[mf][nf][1];
                    const float c2 = sacc[mf][nf][2], c3 = sacc[mf][nf][3];
                    const float x0 = __shfl_sync(0xffffffffu, c0, sh1);
                    const float x1 = __shfl_sync(0xffffffffu, c1, sh1);
                    const float x2 = __shfl_sync(0xffffffffu, c2, sh1);
                    const float x3 = __shfl_sync(0xffffffffu, c3, sh1);
                    const float y0 = __shfl_sync(0xffffffffu, c0, sh2);
                    const float y1 = __shfl_sync(0xffffffffu, c1, sh2);
                    const float y2 = __shfl_sync(0xffffffffu, c2, sh2);
                    const float y3 = __shfl_sync(0xffffffffu, c3, sh2);
                    uint32_t af[4];
                    af[0] = __float_as_uint(odd ? x1 : x0);
                    af[1] = __float_as_uint(odd ? x3 : x2);
                    af[2] = __float_as_uint(odd ? y1 : y0);
                    af[3] = __float_as_uint(odd ? y3 : y2);
                    #pragma unroll
                    for (int dn = 0; dn < 8; dn++)
                        mma8(pv[mf][dn], af, bf[dn]);
                }
            }
        }
    }

    // ---- rowsum -> linv ----
    #pragma unroll
    for (int mf = 0; mf < 2; mf++)
        #pragma unroll
        for (int hf = 0; hf < 2; hf++) {
            rs[mf][hf] += __shfl_xor_sync(0xffffffffu, rs[mf][hf], 1);
            rs[mf][hf] += __shfl_xor_sync(0xffffffffu, rs[mf][hf], 2);
        }
    __syncthreads();
    if (tig == 0) {
        #pragma unroll
        for (int mf = 0; mf < 2; mf++) {
            red[wn * 128 + wm * 32 + mf * 16 + g]     = rs[mf][0];
            red[wn * 128 + wm * 32 + mf * 16 + g + 8] = rs[mf][1];
        }
    }
    __syncthreads();
    if (t < 128) {
        const float li = 1.0f / (red[t] + red[128 + t]);
        g_linv[bh * NTOK + i0 + t] = li;
        linv_s[t] = li;
    }
    // wn1 stages its PV partial into Qs (Q no longer needed)
    if (wn == 1) {
        #pragma unroll
        for (int mf = 0; mf < 2; mf++) {
            const int lr0 = wm * 32 + mf * 16 + g, lr1 = lr0 + 8;
            #pragma unroll
            for (int dn = 0; dn < 8; dn++) {
                const int col = dn * 8 + tig * 2;
                *(float2*)&Qs[lr0][col] = make_float2(pv[mf][dn][0], pv[mf][dn][1]);
                *(float2*)&Qs[lr1][col] = make_float2(pv[mf][dn][2], pv[mf][dn][3]);
            }
        }
    }
    __syncthreads();
    if (wn == 0) {
        float* Ob = g_O + ((size_t)b * CH + h * DHEAD) * NTOK;
        #pragma unroll
        for (int mf = 0; mf < 2; mf++) {
            const int lr0 = wm * 32 + mf * 16 + g, lr1 = lr0 + 8;
            const float li0 = linv_s[lr0], li1 = linv_s[lr1];
            #pragma unroll
            for (int dn = 0; dn < 8; dn++) {
                const int col = dn * 8 + tig * 2;
                Ob[(size_t)col * NTOK + i0 + lr0] =
                    tf32r((pv[mf][dn][0] + Qs[lr0][col]) * li0);
                Ob[(size_t)(col + 1) * NTOK + i0 + lr0] =
                    tf32r((pv[mf][dn][1] + Qs[lr0][col + 1]) * li0);
                Ob[(size_t)col * NTOK + i0 + lr1] =
                    tf32r((pv[mf][dn][2] + Qs[lr1][col]) * li1);
                Ob[(size_t)(col + 1) * NTOK + i0 + lr1] =
                    tf32r((pv[mf][dn][3] + Qs[lr1][col + 1]) * li1);
            }
        }
    }
}

// ---------------------------------------------------------------------------
extern "C" void kernel_launch(void* const* d_in, const int* in_sizes, int n_in,
                              void* d_out, int out_size) {
    const float* query   = (const float*)d_in[0];
    const float* context = (const float*)d_in[1];
    const float* Wq      = (const float*)d_in[2];
    const float* Wk      = (const float*)d_in[3];
    const float* Wv      = (const float*)d_in[4];
    const float* Wo      = (const float*)d_in[5];
    const float* bo      = (const float*)d_in[6];
    float* out = (float*)d_out;

    const int SM_MM   = (2*128*36 + 2*32*136) * 4;   // 71680
    const int SM_ATTN = 44928 * 4;                   // 179712
    cudaFuncSetAttribute(k_mm,   cudaFuncAttributeMaxDynamicSharedMemorySize, SM_MM);
    cudaFuncSetAttribute(k_attn, cudaFuncAttributeMaxDynamicSharedMemorySize, SM_ATTN);

    float *pXq, *pXc, *pWq, *pWk, *pWv, *pWo, *pQt, *pKc, *pVt, *pO;
    cudaGetSymbolAddress((void**)&pXq, g_Xq);
    cudaGetSymbolAddress((void**)&pXc, g_Xc);
    cudaGetSymbolAddress((void**)&pWq, g_Wq);
    cudaGetSymbolAddress((void**)&pWk, g_Wk);
    cudaGetSymbolAddress((void**)&pWv, g_Wv);
    cudaGetSymbolAddress((void**)&pWo, g_Wo);
    cudaGetSymbolAddress((void**)&pQt, g_Qt);
    cudaGetSymbolAddress((void**)&pKc, g_Kc);
    cudaGetSymbolAddress((void**)&pVt, g_Vt);
    cudaGetSymbolAddress((void**)&pO,  g_O);

    k_round2<<<dim3(BATCH * CH * NTOK / 1024, 2), 256>>>(query, context);
    k_roundW<<<dim3(CH * CH / 1024, 4), 256>>>(Wq, Wk, Wv, Wo);

    MMArgs a1;
    a1.A[0] = pWq; a1.B[0] = pXq; a1.Y[0] = pQt; a1.mode[0] = 0;
    a1.A[1] = pWk; a1.B[1] = pXc; a1.Y[1] = pKc; a1.mode[1] = 1;
    a1.A[2] = pWv; a1.B[2] = pXc; a1.Y[2] = pVt; a1.mode[2] = 0;
    a1.bias = nullptr;
    k_mm<<<dim3(8, 3, 24), 256, SM_MM>>>(a1);

    k_attn<<<dim3(8, BH), 256, SM_ATTN>>>();
    k_colsum<<<dim3(8, BH), 256>>>();

    MMArgs a2;
    a2.A[0] = pWo; a2.B[0] = pO; a2.Y[0] = out; a2.mode[0] = 2;
    a2.A[1] = a2.A[2] = nullptr; a2.B[1] = a2.B[2] = nullptr;
    a2.Y[1] = a2.Y[2] = nullptr; a2.mode[1] = a2.mode[2] = 0;
    a2.bias = bo;
    k_mm<<<dim3(8, 3, 8), 256, SM_MM>>>(a2);

    k_amap<<<BATCH * NTOK / 256, 256>>>(out);
}

// round 17
// speedup vs baseline: 1.6955x; 1.0217x over previous
#include <cuda_runtime.h>
#include <cuda_bf16.h>
#include <cstdint>

#define BATCH 8
#define CH    384
#define NHEAD 6
#define DHEAD 64
#define NTOK  1024
#define BH    (BATCH*NHEAD)

// scratch (GEMM operands pre-rounded to tf32; E stored bf16 for attn-map only)
__device__ float g_Xq[BATCH*CH*NTOK];
__device__ float g_Xc[BATCH*CH*NTOK];
__device__ float g_Wq[CH*CH];
__device__ float g_Wk[CH*CH];
__device__ float g_Wv[CH*CH];
__device__ float g_Wo[CH*CH];
__device__ float g_Qt[BATCH*NTOK*CH];                 // token-major [b][n][inner]
__device__ float g_Kc[BATCH*CH*NTOK];                 // channel-major
__device__ float g_Vt[BATCH*NTOK*CH];                 // token-major
__device__ float g_O [BATCH*CH*NTOK];                 // channel-major
__device__ __nv_bfloat16 g_Eb[(size_t)BH*NTOK*NTOK];  // exp(logits) bf16 (colsum only)
__device__ float g_linv[BH*NTOK];
__device__ float g_colsum[BATCH*NTOK];

__device__ __forceinline__ uint32_t smem_u32(const void* p) {
    uint32_t a;
    asm("{ .reg .u64 t; cvta.to.shared.u64 t, %1; cvt.u32.u64 %0, t; }" : "=r"(a) : "l"(p));
    return a;
}
__device__ __forceinline__ float tf32r(float x) {
    uint32_t b;
    asm("cvt.rna.tf32.f32 %0, %1;" : "=r"(b) : "f"(x));
    return __uint_as_float(b);
}
__device__ __forceinline__ void cpa16(uint32_t d, const void* s) {
    asm volatile("cp.async.ca.shared.global [%0], [%1], 16;" :: "r"(d), "l"(s));
}
#define CP_COMMIT() asm volatile("cp.async.commit_group;" ::: "memory")
#define CP_WAIT1()  asm volatile("cp.async.wait_group 1;" ::: "memory")
#define CP_WAIT0()  asm volatile("cp.async.wait_group 0;" ::: "memory")

__device__ __forceinline__ void mma8(float* d, const uint32_t* a, const uint32_t* b) {
    asm volatile("mma.sync.aligned.m16n8k8.row.col.f32.tf32.tf32.f32 "
        "{%0,%1,%2,%3}, {%4,%5,%6,%7}, {%8,%9}, {%0,%1,%2,%3};"
        : "+f"(d[0]), "+f"(d[1]), "+f"(d[2]), "+f"(d[3])
        : "r"(a[0]), "r"(a[1]), "r"(a[2]), "r"(a[3]), "r"(b[0]), "r"(b[1]));
}
#define LDU(p) (*(const uint32_t*)(p))

// ---------------------------------------------------------------------------
// single rounding launch: y=0 -> Xq (+zero colsum), y=1 -> Xc, y=2 -> weights
__global__ void k_roundall(const float* __restrict__ q, const float* __restrict__ c,
                           const float* __restrict__ wq, const float* __restrict__ wk,
                           const float* __restrict__ wv, const float* __restrict__ wo) {
    const int y = blockIdx.y;
    const size_t i4 = (size_t)blockIdx.x * 256 + threadIdx.x;
    if (y == 2) {
        if (i4 >= (size_t)CH * CH) return;            // 147456 float4 total (4 weights)
        const int w = (int)(i4 / (CH * CH / 4));      // 36864 f4 per weight
        const size_t off = i4 % (CH * CH / 4);
        const float* s; float* d;
        switch (w) {
            case 0: s = wq; d = g_Wq; break;
            case 1: s = wk; d = g_Wk; break;
            case 2: s = wv; d = g_Wv; break;
            default: s = wo; d = g_Wo; break;
        }
        float4 v = *((const float4*)s + off);
        v.x = tf32r(v.x); v.y = tf32r(v.y); v.z = tf32r(v.z); v.w = tf32r(v.w);
        *((float4*)d + off) = v;
        return;
    }
    const float* s = y ? c : q;
    float* d = y ? g_Xc : g_Xq;
    float4 v = *((const float4*)s + i4);
    v.x = tf32r(v.x); v.y = tf32r(v.y); v.z = tf32r(v.z); v.w = tf32r(v.w);
    *((float4*)d + i4) = v;
    if (y == 0 && i4 < BATCH * NTOK / 4)
        *((float4*)g_colsum + i4) = make_float4(0.f, 0.f, 0.f, 0.f);
}

__global__ void k_amap(float* __restrict__ out) {
    const int idx = blockIdx.x * 256 + threadIdx.x;
    out[(size_t)BATCH * CH * NTOK + idx] = g_colsum[idx] * (1.0f / (NHEAD * NTOK));
}

// colsum from bf16 E (attn-map path): colsum[b][j] += sum_i E[i][j]*linv[i]
__global__ __launch_bounds__(256) void k_colsum() {
    __shared__ float rx[256], ry[256];
    const int t = threadIdx.x;
    const int bh = blockIdx.y, b = bh / NHEAD;
    const int jj = blockIdx.x * 64 + (t & 63);
    const int q = t >> 6;
    const __nv_bfloat162* E2 =
        (const __nv_bfloat162*)(g_Eb + (size_t)bh * NTOK * NTOK);
    const float* li = g_linv + bh * NTOK;
    float sx = 0.f, sy = 0.f;
    for (int i = q * 256; i < q * 256 + 256; i++) {
        const __nv_bfloat162 e = E2[(size_t)i * 512 + jj];
        const float l = li[i];
        sx += __bfloat162float(e.x) * l;
        sy += __bfloat162float(e.y) * l;
    }
    rx[t] = sx; ry[t] = sy;
    __syncthreads();
    if (t < 64) {
        const float vx = rx[t] + rx[t + 64] + rx[t + 128] + rx[t + 192];
        const float vy = ry[t] + ry[t + 64] + ry[t + 128] + ry[t + 192];
        const int j = blockIdx.x * 128 + t * 2;
        atomicAdd(&g_colsum[b * NTOK + j], vx);
        atomicAdd(&g_colsum[b * NTOK + j + 1], vy);
    }
}

// ---------------------------------------------------------------------------
// Fused projection GEMMs. D[m][n] = sum_k A[m][k]*B[b][k][n]. grid z = nw*BATCH.
// mode 0: token-major tf32 (smem-staged coalesced epilogue);
// mode 1: channel-major tf32; mode 2: channel-major + bias raw
struct MMArgs {
    const float* A[3]; const float* B[3]; float* Y[3];
    const float* bias; int mode[3];
};

__global__ __launch_bounds__(256, 2)
void k_mm(MMArgs args) {
    extern __shared__ float sm[];
    float (*As)[36]  = (float(*)[36])sm;               // [2][128][36]
    float (*Bs)[136] = (float(*)[136])(sm + 2*128*36); // [2][32][136]
    const uint32_t sbA = smem_u32(sm), sbB = smem_u32(sm + 2*128*36);

    const int t = threadIdx.x, lane = t & 31, wid = t >> 5;
    const int g = lane >> 2, tig = lane & 3;
    const int wm = wid >> 1, wn = wid & 1;
    const int w = blockIdx.z / BATCH, b = blockIdx.z % BATCH;
    const int n0 = blockIdx.x * 128, m0 = blockIdx.y * 128;
    const float* Aw = args.A[w];
    const float* Bb = args.B[w] + (size_t)b * CH * NTOK;
    const int mode = args.mode[w];

    float acc[2][8][4] = {};

    #pragma unroll
    for (int it = 0; it < 4; it++) {
        const int idx = t + 256 * it, r = idx >> 3, f = idx & 7;
        cpa16(sbA + (r * 36 + f * 4) * 4, &Aw[(size_t)(m0 + r) * CH + f * 4]);
    }
    #pragma unroll
    for (int it = 0; it < 4; it++) {
        const int idx = t + 256 * it, r = idx >> 5, f = idx & 31;
        cpa16(sbB + (r * 136 + f * 4) * 4, &Bb[(size_t)r * NTOK + n0 + f * 4]);
    }
    CP_COMMIT();

    for (int c = 0; c < 12; c++) {
        const int buf = c & 1;
        if (c + 1 < 12) {
            const int k1 = (c + 1) * 32, nb = (c + 1) & 1;
            #pragma unroll
            for (int it = 0; it < 4; it++) {
                const int idx = t + 256 * it, r = idx >> 3, f = idx & 7;
                cpa16(sbA + nb * 18432 + (r * 36 + f * 4) * 4,
                      &Aw[(size_t)(m0 + r) * CH + k1 + f * 4]);
            }
            #pragma unroll
            for (int it = 0; it < 4; it++) {
                const int idx = t + 256 * it, r = idx >> 5, f = idx & 31;
                cpa16(sbB + nb * 17408 + (r * 136 + f * 4) * 4,
                      &Bb[(size_t)(k1 + r) * NTOK + n0 + f * 4]);
            }
            CP_COMMIT();
            CP_WAIT1();
        } else {
            CP_WAIT0();
        }
        __syncthreads();
        #pragma unroll
        for (int ks = 0; ks < 4; ks++) {
            const int kk = ks * 8;
            uint32_t af[2][4], bf[8][2];
            #pragma unroll
            for (int mf = 0; mf < 2; mf++) {
                const int rb = buf * 128 + wm * 32 + mf * 16 + g;
                af[mf][0] = LDU(&As[rb][kk + tig]);
                af[mf][1] = LDU(&As[rb + 8][kk + tig]);
                af[mf][2] = LDU(&As[rb][kk + tig + 4]);
                af[mf][3] = LDU(&As[rb + 8][kk + tig + 4]);
            }
            #pragma unroll
            for (int nf = 0; nf < 8; nf++) {
                const int col = wn * 64 + nf * 8 + g;
                bf[nf][0] = LDU(&Bs[buf * 32 + kk + tig][col]);
                bf[nf][1] = LDU(&Bs[buf * 32 + kk + tig + 4][col]);
            }
            #pragma unroll
            for (int mf = 0; mf < 2; mf++)
                #pragma unroll
                for (int nf = 0; nf < 8; nf++)
                    mma8(acc[mf][nf], af[mf], bf[nf]);
        }
        __syncthreads();
    }

    if (mode == 0) {
        float* stage = sm;   // 128 rows x stride 132 = 16896 floats
        #pragma unroll
        for (int mf = 0; mf < 2; mf++) {
            const int r0 = wm * 32 + mf * 16 + g, r1 = r0 + 8;
            #pragma unroll
            for (int nf = 0; nf < 8; nf++) {
                const int col = wn * 64 + nf * 8 + tig * 2;
                stage[(col    ) * 132 + r0] = tf32r(acc[mf][nf][0]);
                stage[(col + 1) * 132 + r0] = tf32r(acc[mf][nf][1]);
                stage[(col    ) * 132 + r1] = tf32r(acc[mf][nf][2]);
                stage[(col + 1) * 132 + r1] = tf32r(acc[mf][nf][3]);
            }
        }
        __syncthreads();
        float* Yb = args.Y[w] + (size_t)b * NTOK * CH;
        #pragma unroll
        for (int it = 0; it < 16; it++) {
            const int idx = t + 256 * it, n = idx >> 5, fm = idx & 31;
            *(float4*)&Yb[(size_t)(n0 + n) * CH + m0 + fm * 4] =
                *(float4*)&stage[n * 132 + fm * 4];
        }
    } else {
        float* Yb = args.Y[w] + (size_t)b * CH * NTOK;
        const bool wb = (mode == 2);
        #pragma unroll
        for (int mf = 0; mf < 2; mf++) {
            const int r0 = m0 + wm * 32 + mf * 16 + g, r1 = r0 + 8;
            const float b0 = wb ? args.bias[r0] : 0.0f;
            const float b1 = wb ? args.bias[r1] : 0.0f;
            #pragma unroll
            for (int nf = 0; nf < 8; nf++) {
                const int col = n0 + wn * 64 + nf * 8 + tig * 2;
                float2 v0, v1;
                if (wb) {
                    v0 = make_float2(acc[mf][nf][0] + b0, acc[mf][nf][1] + b0);
                    v1 = make_float2(acc[mf][nf][2] + b1, acc[mf][nf][3] + b1);
                } else {
                    v0 = make_float2(tf32r(acc[mf][nf][0]), tf32r(acc[mf][nf][1]));
                    v1 = make_float2(tf32r(acc[mf][nf][2]), tf32r(acc[mf][nf][3]));
                }
                *(float2*)&Yb[(size_t)r0 * NTOK + col] = v0;
                *(float2*)&Yb[(size_t)r1 * NTOK + col] = v1;
            }
        }
    }
}

// ---------------------------------------------------------------------------
// Fused attention (R14/R16 best: 256 thr, 8 warps 4wm x 2wn, warp 32i x 64j,
// two nf-halves per j-tile, double-buffered K/V, occ 1).
__global__ __launch_bounds__(256, 1)
void k_attn() {
    extern __shared__ float sm[];
    float (*Qs)[68]  = (float(*)[68])sm;
    float (*Ks)[136] = (float(*)[136])(sm + 8704);
    float (*Vs)[72]  = (float(*)[72])(sm + 26112);
    float* red    = sm + 44544;
    float* linv_s = sm + 44800;
    const uint32_t sbK = smem_u32(sm + 8704), sbV = smem_u32(sm + 26112);

    const int t = threadIdx.x, lane = t & 31, wid = t >> 5;
    const int g = lane >> 2, tig = lane & 3;
    const int wm = wid >> 1, wn = wid & 1;
    const int bh = blockIdx.y, b = bh / NHEAD, h = bh % NHEAD;
    const int i0 = blockIdx.x * 128;
    const float* Qb = g_Qt + (size_t)b * NTOK * CH + h * DHEAD;
    const float* Kb = g_Kc + (size_t)b * CH * NTOK + (size_t)h * DHEAD * NTOK;
    const float* Vb = g_Vt + (size_t)b * NTOK * CH + h * DHEAD;
    __nv_bfloat16* Eb = g_Eb + (size_t)bh * NTOK * NTOK;

    #pragma unroll
    for (int it = 0; it < 8; it++) {
        const int idx = t + 256 * it, r = idx >> 4, f = idx & 15;
        *(float4*)&Qs[r][f * 4] = *(const float4*)&Qb[(size_t)(i0 + r) * CH + f * 4];
    }
    #pragma unroll
    for (int it = 0; it < 8; it++) {
        const int idx = t + 256 * it, r = idx >> 5, f = idx & 31;
        cpa16(sbK + (r * 136 + f * 4) * 4, &Kb[(size_t)r * NTOK + f * 4]);
    }
    #pragma unroll
    for (int it = 0; it < 8; it++) {
        const int idx = t + 256 * it, r = idx >> 4, f = idx & 15;
        cpa16(sbV + (r * 72 + f * 4) * 4, &Vb[(size_t)r * CH + f * 4]);
    }
    CP_COMMIT();

    float pv[2][8][4] = {};
    float rs[2][2] = {};
    const int sh1 = (lane & ~3) + (tig >> 1), sh2 = sh1 + 2;
    const bool odd = tig & 1;

    for (int jt = 0; jt < 8; jt++) {
        const int j0 = jt * 128, buf = jt & 1;
        CP_WAIT0();
        __syncthreads();

        if (jt + 1 < 8) {
            const int j1 = (jt + 1) * 128, nb = (jt + 1) & 1;
            #pragma unroll
            for (int it = 0; it < 8; it++) {
                const int idx = t + 256 * it, r = idx >> 5, f = idx & 31;
                cpa16(sbK + nb * 34816 + (r * 136 + f * 4) * 4,
                      &Kb[(size_t)r * NTOK + j1 + f * 4]);
            }
            #pragma unroll
            for (int it = 0; it < 8; it++) {
                const int idx = t + 256 * it, r = idx >> 4, f = idx & 15;
                cpa16(sbV + nb * 36864 + (r * 72 + f * 4) * 4,
                      &Vb[(size_t)(j1 + r) * CH + f * 4]);
            }
            CP_COMMIT();
        }

        #pragma unroll
        for (int half = 0; half < 2; half++) {
            float sacc[2][4][4] = {};
            #pragma unroll
            for (int ks = 0; ks < 8; ks++) {
                const int kk = ks * 8;
                uint32_t af[2][4], bf[4][2];
                #pragma unroll
                for (int mf = 0; mf < 2; mf++) {
                    const int rb = wm * 32 + mf * 16 + g;
                    af[mf][0] = LDU(&Qs[rb][kk + tig]);
                    af[mf][1] = LDU(&Qs[rb + 8][kk + tig]);
                    af[mf][2] = LDU(&Qs[rb][kk + tig + 4]);
                    af[mf][3] = LDU(&Qs[rb + 8][kk + tig + 4]);
                }
                #pragma unroll
                for (int nf = 0; nf < 4; nf++) {
                    const int col = wn * 64 + (half * 4 + nf) * 8 + g;
                    bf[nf][0] = LDU(&Ks[buf * 64 + kk + tig][col]);
                    bf[nf][1] = LDU(&Ks[buf * 64 + kk + tig + 4][col]);
                }
                #pragma unroll
                for (int mf = 0; mf < 2; mf++)
                    #pragma unroll
                    for (int nf = 0; nf < 4; nf++)
                        mma8(sacc[mf][nf], af[mf], bf[nf]);
            }

            #pragma unroll
            for (int mf = 0; mf < 2; mf++) {
                const int r0 = wm * 32 + mf * 16 + g, r1 = r0 + 8;
                #pragma unroll
                for (int nf = 0; nf < 4; nf++) {
                    const int col = j0 + wn * 64 + (half * 4 + nf) * 8 + tig * 2;
                    const float e0 = __expf(sacc[mf][nf][0] * 0.125f);
                    const float e1 = __expf(sacc[mf][nf][1] * 0.125f);
                    const float e2 = __expf(sacc[mf][nf][2] * 0.125f);
                    const float e3 = __expf(sacc[mf][nf][3] * 0.125f);
                    rs[mf][0] += e0 + e1;
                    rs[mf][1] += e2 + e3;
                    *(__nv_bfloat162*)&Eb[(size_t)(i0 + r0) * NTOK + col] =
                        __floats2bfloat162_rn(e0, e1);
                    *(__nv_bfloat162*)&Eb[(size_t)(i0 + r1) * NTOK + col] =
                        __floats2bfloat162_rn(e2, e3);
                    sacc[mf][nf][0] = tf32r(e0);
                    sacc[mf][nf][1] = tf32r(e1);
                    sacc[mf][nf][2] = tf32r(e2);
                    sacc[mf][nf][3] = tf32r(e3);
                }
            }

            #pragma unroll
            for (int nf = 0; nf < 4; nf++) {
                const int kp = wn * 64 + (half * 4 + nf) * 8;
                uint32_t bf[8][2];
                #pragma unroll
                for (int dn = 0; dn < 8; dn++) {
                    bf[dn][0] = LDU(&Vs[buf * 128 + kp + tig][dn * 8 + g]);
                    bf[dn][1] = LDU(&Vs[buf * 128 + kp + tig + 4][dn * 8 + g]);
                }
                #pragma unroll
                for (int mf = 0; mf < 2; mf++) {
                    const float c0 = sacc[mf][nf][0], c1 = sacc[mf][nf][1];
                    const float c2 = sacc[mf][nf][2], c3 = sacc[mf][nf][3];
                    const float x0 = __shfl_sync(0xffffffffu, c0, sh1);
                    const float x1 = __shfl_sync(0xffffffffu, c1, sh1);
                    const float x2 = __shfl_sync(0xffffffffu, c2, sh1);
                    const float x3 = __shfl_sync(0xffffffffu, c3, sh1);
                    const float y0 = __shfl_sync(0xffffffffu, c0, sh2);
                    const float y1 = __shfl_sync(0xffffffffu, c1, sh2);
                    const float y2 = __shfl_sync(0xffffffffu, c2, sh2);
                    const float y3 = __shfl_sync(0xffffffffu, c3, sh2);
                    uint32_t af[4];
                    af[0] = __float_as_uint(odd ? x1 : x0);
                    af[1] = __float_as_uint(odd ? x3 : x2);
                    af[2] = __float_as_uint(odd ? y1 : y0);
                    af[3] = __float_as_uint(odd ? y3 : y2);
                    #pragma unroll
                    for (int dn = 0; dn < 8; dn++)
                        mma8(pv[mf][dn], af, bf[dn]);
                }
            }
        }
    }

    #pragma unroll
    for (int mf = 0; mf < 2; mf++)
        #pragma unroll
        for (int hf = 0; hf < 2; hf++) {
            rs[mf][hf] += __shfl_xor_sync(0xffffffffu, rs[mf][hf], 1);
            rs[mf][hf] += __shfl_xor_sync(0xffffffffu, rs[mf][hf], 2);
        }
    __syncthreads();
    if (tig == 0) {
        #pragma unroll
        for (int mf = 0; mf < 2; mf++) {
            red[wn * 128 + wm * 32 + mf * 16 + g]     = rs[mf][0];
            red[wn * 128 + wm * 32 + mf * 16 + g + 8] = rs[mf][1];
        }
    }
    __syncthreads();
    if (t < 128) {
        const float li = 1.0f / (red[t] + red[128 + t]);
        g_linv[bh * NTOK + i0 + t] = li;
        linv_s[t] = li;
    }
    if (wn == 1) {
        #pragma unroll
        for (int mf = 0; mf < 2; mf++) {
            const int lr0 = wm * 32 + mf * 16 + g, lr1 = lr0 + 8;
            #pragma unroll
            for (int dn = 0; dn < 8; dn++) {
                const int col = dn * 8 + tig * 2;
                *(float2*)&Qs[lr0][col] = make_float2(pv[mf][dn][0], pv[mf][dn][1]);
                *(float2*)&Qs[lr1][col] = make_float2(pv[mf][dn][2], pv[mf][dn][3]);
            }
        }
    }
    __syncthreads();
    if (wn == 0) {
        float* Ob = g_O + ((size_t)b * CH + h * DHEAD) * NTOK;
        #pragma unroll
        for (int mf = 0; mf < 2; mf++) {
            const int lr0 = wm * 32 + mf * 16 + g, lr1 = lr0 + 8;
            const float li0 = linv_s[lr0], li1 = linv_s[lr1];
            #pragma unroll
            for (int dn = 0; dn < 8; dn++) {
                const int col = dn * 8 + tig * 2;
                Ob[(size_t)col * NTOK + i0 + lr0] =
                    tf32r((pv[mf][dn][0] + Qs[lr0][col]) * li0);
                Ob[(size_t)(col + 1) * NTOK + i0 + lr0] =
                    tf32r((pv[mf][dn][1] + Qs[lr0][col + 1]) * li0);
                Ob[(size_t)col * NTOK + i0 + lr1] =
                    tf32r((pv[mf][dn][2] + Qs[lr1][col]) * li1);
                Ob[(size_t)(col + 1) * NTOK + i0 + lr1] =
                    tf32r((pv[mf][dn][3] + Qs[lr1][col + 1]) * li1);
            }
        }
    }
}

// ---------------------------------------------------------------------------
extern "C" void kernel_launch(void* const* d_in, const int* in_sizes, int n_in,
                              void* d_out, int out_size) {
    const float* query   = (const float*)d_in[0];
    const float* context = (const float*)d_in[1];
    const float* Wq      = (const float*)d_in[2];
    const float* Wk      = (const float*)d_in[3];
    const float* Wv      = (const float*)d_in[4];
    const float* Wo      = (const float*)d_in[5];
    const float* bo      = (const float*)d_in[6];
    float* out = (float*)d_out;

    const int SM_MM   = (2*128*36 + 2*32*136) * 4;   // 71680
    const int SM_ATTN = 44928 * 4;                   // 179712

    static cudaStream_t s2 = nullptr;
    static cudaEvent_t evF = nullptr, evJ = nullptr;
    if (!s2) {   // one-time infra init (correctness call, outside capture)
        cudaFuncSetAttribute(k_mm,   cudaFuncAttributeMaxDynamicSharedMemorySize, SM_MM);
        cudaFuncSetAttribute(k_attn, cudaFuncAttributeMaxDynamicSharedMemorySize, SM_ATTN);
        cudaStreamCreateWithFlags(&s2, cudaStreamNonBlocking);
        cudaEventCreateWithFlags(&evF, cudaEventDisableTiming);
        cudaEventCreateWithFlags(&evJ, cudaEventDisableTiming);
    }

    float *pXq, *pXc, *pWq, *pWk, *pWv, *pWo, *pQt, *pKc, *pVt, *pO;
    cudaGetSymbolAddress((void**)&pXq, g_Xq);
    cudaGetSymbolAddress((void**)&pXc, g_Xc);
    cudaGetSymbolAddress((void**)&pWq, g_Wq);
    cudaGetSymbolAddress((void**)&pWk, g_Wk);
    cudaGetSymbolAddress((void**)&pWv, g_Wv);
    cudaGetSymbolAddress((void**)&pWo, g_Wo);
    cudaGetSymbolAddress((void**)&pQt, g_Qt);
    cudaGetSymbolAddress((void**)&pKc, g_Kc);
    cudaGetSymbolAddress((void**)&pVt, g_Vt);
    cudaGetSymbolAddress((void**)&pO,  g_O);

    k_roundall<<<dim3(BATCH * CH * NTOK / 1024, 3), 256>>>(query, context,
                                                           Wq, Wk, Wv, Wo);

    MMArgs a1;
    a1.A[0] = pWq; a1.B[0] = pXq; a1.Y[0] = pQt; a1.mode[0] = 0;
    a1.A[1] = pWk; a1.B[1] = pXc; a1.Y[1] = pKc; a1.mode[1] = 1;
    a1.A[2] = pWv; a1.B[2] = pXc; a1.Y[2] = pVt; a1.mode[2] = 0;
    a1.bias = nullptr;
    k_mm<<<dim3(8, 3, 24), 256, SM_MM>>>(a1);

    k_attn<<<dim3(8, BH), 256, SM_ATTN>>>();

    // fork: colsum + amap on s2, overlapped with the output projection
    cudaEventRecord(evF, 0);
    cudaStreamWaitEvent(s2, evF, 0);
    k_colsum<<<dim3(8, BH), 256, 0, s2>>>();
    k_amap<<<BATCH * NTOK / 256, 256, 0, s2>>>(out);
    cudaEventRecord(evJ, s2);

    MMArgs a2;
    a2.A[0] = pWo; a2.B[0] = pO; a2.Y[0] = out; a2.mode[0] = 2;
    a2.A[1] = a2.A[2] = nullptr; a2.B[1] = a2.B[2] = nullptr;
    a2.Y[1] = a2.Y[2] = nullptr; a2.mode[1] = a2.mode[2] = 0;
    a2.bias = bo;
    k_mm<<<dim3(8, 3, 8), 256, SM_MM>>>(a2);

    // join before returning to the harness
    cudaStreamWaitEvent(0, evJ, 0);
}